// round 13
// baseline (speedup 1.0000x reference)
#include <cuda_runtime.h>
#include <stdint.h>

// Integrate-and-fire, sequential-equivalent of the reference:
//   per neuron: v=0 at t=0 and t=100; v += x[t]; if (v>2) {spike=1; v=0;}
// in  (4,200,64,64,8):  in[b][t][h1][h2][c],  stride_t=32768
// out (4,200,64,8,64):  out[b][t][h2][c][h1], stride_t=32768
//
// Grid 1024 = (b:4, h2:64, chunk:2, h1-half:2) x 256 threads, 1 neuron per
// thread, one 100-step chunk. __launch_bounds__(256,8): regs <= 32 -> 8
// blocks/SM -> capacity 1184 >= 1024: single wave at ~55 warps/SM.
//
// R12 change: TWO 4-step phases per barrier (13 barriers instead of 25).
// Interleaved consume/refill keeps data registers at 8 (x0[4]/x1[4] each
// refilled immediately after being packed), so residency is unchanged.
//   scan role: tid=(h1l*8+c) -> coalesced LDG.32 (__ldcs streaming),
//     register membrane scan, 4 spikes -> 1 byte-packed uint32 per phase,
//     2 STS.32 per group (swizzle word = c*32 + (h1l ^ 4c): conflict-free).
//   store role: tid=(k4*64+c*8+h1q) -> LDS.128 of 4 packed words, extract
//     byte k4, STG.128 via __stcs (fully coalesced 128B segments).
// Parity double-buffered smem (reuse distance 2 groups -> 1 bar/group).

#define T_STRIDE 32768

__device__ __forceinline__ float4 unpack4(uint4 a, int sh) {
    float4 f;
    f.x = __uint_as_float(((a.x >> sh) & 1u) * 0x3f800000u);
    f.y = __uint_as_float(((a.y >> sh) & 1u) * 0x3f800000u);
    f.z = __uint_as_float(((a.z >> sh) & 1u) * 0x3f800000u);
    f.w = __uint_as_float(((a.w >> sh) & 1u) * 0x3f800000u);
    return f;
}

#define STEP(W, XV, BIT) do { v += (XV); if (v > 2.0f) { (W) |= (BIT); v = 0.0f; } } while (0)

// Pack one 4-step phase from buffer CUR into word W (membrane chain in v).
#define PACK4(CUR, W) do {                                                    \
    (W) = 0u;                                                                 \
    STEP(W, CUR[0], 1u);        STEP(W, CUR[1], 1u << 8);                     \
    STEP(W, CUR[2], 1u << 16);  STEP(W, CUR[3], 1u << 24);                    \
} while (0)

__global__ __launch_bounds__(256, 8)
void iaf_kernel(const float* __restrict__ in, float* __restrict__ out) {
    const int bid   = blockIdx.x;            // 1024 = b(4) x h2(64) x chunk(2) x half(2)
    const int b     = bid >> 8;
    const int h2    = (bid >> 2) & 63;
    const int chunk = (bid >> 1) & 1;
    const int half  = bid & 1;
    const int tid   = threadIdx.x;

    // scan mapping (load-coalesced)
    const int h1l = tid >> 3;                // 0..31 (local h1 within half)
    const int c_s = tid & 7;                 // 0..7
    // store mapping
    const int k4  = tid >> 6;                // 0..3 (byte within packed word)
    const int c_o = (tid >> 3) & 7;          // 0..7
    const int h1q = tid & 7;                 // 0..7 (float4 group within 32 h1)

    __shared__ __align__(16) uint32_t sp[2][2][256];  // [parity][plane][word]

    const size_t tb = (size_t)(b * 200 + chunk * 100) * T_STRIDE;
    const float* inp  = in  + tb + (half * 32 + h1l) * 512 + h2 * 8 + c_s;
    float*       outp = out + tb + h2 * 512 + c_o * 64 + half * 32 + h1q * 4;

    const int sts = c_s * 32 + (h1l ^ (c_s << 2));     // conflict-free STS
    const int lds = c_o * 32 + ((h1q ^ c_o) << 2);     // 16B-aligned LDS.128
    const int sh  = k4 * 8;

    float x0[4], x1[4];

    // prologue: phases 0 and 1
    #pragma unroll
    for (int k = 0; k < 4; k++) x0[k] = __ldcs(inp + (size_t)k * T_STRIDE);
    #pragma unroll
    for (int k = 0; k < 4; k++) x1[k] = __ldcs(inp + (size_t)(4 + k) * T_STRIDE);

    float v = 0.0f;

    // 12 groups of 2 phases (phases 0..23) + tail phase 24.
    for (int g = 0; g < 12; g++) {
        const int p0  = 2 * g;
        const int par = g & 1;
        uint32_t w0, w1;

        // pack phase p0, then immediately refill x0 with phase p0+2
        PACK4(x0, w0);
        {
            const float* np = inp + (size_t)(p0 + 2) * (4 * T_STRIDE);
            #pragma unroll
            for (int k = 0; k < 4; k++) x0[k] = __ldcs(np + (size_t)k * T_STRIDE);
        }

        // pack phase p0+1, then refill x1 with phase p0+3 (last group: none)
        PACK4(x1, w1);
        if (g < 11) {
            const float* np = inp + (size_t)(p0 + 3) * (4 * T_STRIDE);
            #pragma unroll
            for (int k = 0; k < 4; k++) x1[k] = __ldcs(np + (size_t)k * T_STRIDE);
        }

        sp[par][0][sts] = w0;
        sp[par][1][sts] = w1;
        __syncthreads();

        uint4 a0 = *(const uint4*)&sp[par][0][lds];
        __stcs((float4*)(outp + (size_t)(p0 * 4 + k4) * T_STRIDE), unpack4(a0, sh));
        uint4 a1 = *(const uint4*)&sp[par][1][lds];
        __stcs((float4*)(outp + (size_t)((p0 + 1) * 4 + k4) * T_STRIDE), unpack4(a1, sh));
    }

    // tail: phase 24 (t=96..99 of this chunk), data already in x0.
    // Last group (g=11) used parity 1; parity-0 plane-0 was last written in
    // group 10, whose readers completed before group 11's barrier -> safe.
    {
        uint32_t w0;
        PACK4(x0, w0);
        sp[0][0][sts] = w0;
        __syncthreads();
        uint4 a0 = *(const uint4*)&sp[0][0][lds];
        __stcs((float4*)(outp + (size_t)(96 + k4) * T_STRIDE), unpack4(a0, sh));
    }
}

extern "C" void kernel_launch(void* const* d_in, const int* in_sizes, int n_in,
                              void* d_out, int out_size) {
    const float* in  = (const float*)d_in[0];
    float*       out = (float*)d_out;
    iaf_kernel<<<1024, 256>>>(in, out);
}